// round 4
// baseline (speedup 1.0000x reference)
#include <cuda_runtime.h>
#include <cuda_bf16.h>

#define TLEN 2048
#define H 20
typedef unsigned long long ull;

// ---- packed f32x2 helpers ----
__device__ __forceinline__ ull pk(float lo, float hi) {
    ull r; asm("mov.b64 %0, {%1, %2};" : "=l"(r) : "f"(lo), "f"(hi)); return r;
}
__device__ __forceinline__ float2 upk(ull v) {
    float2 f; asm("mov.b64 {%0, %1}, %2;" : "=f"(f.x), "=f"(f.y) : "l"(v)); return f;
}
__device__ __forceinline__ ull fma2(ull a, ull b, ull c) {
    ull d; asm("fma.rn.f32x2 %0, %1, %2, %3;" : "=l"(d) : "l"(a), "l"(b), "l"(c)); return d;
}

// z pre-scaled by 2*log2(e): tanh(a) = 1 - 2/(exp2(z) + 1). |z|<~20: safe.
__device__ __forceinline__ float tanh_ps(float z) {
    float e; asm("ex2.approx.f32 %0, %1;" : "=f"(e) : "f"(z));
    float r; asm("rcp.approx.f32 %0, %1;" : "=f"(r) : "f"(e + 1.0f));
    return fmaf(-2.0f, r, 1.0f);
}
__device__ __forceinline__ float sigmoid1(float z) {
    float e; asm("ex2.approx.f32 %0, %1;" : "=f"(e) : "f"(z * -1.4426950408889634f));
    float r; asm("rcp.approx.f32 %0, %1;" : "=f"(r) : "f"(e + 1.0f));
    return r;
}

// 4 threads per batch (quad). Thread q owns hidden rows [5q, 5q+5).
// Dot products run packed over K: (w_k,w_{k+1})*(h_k,h_{k+1}) via fma.rn.f32x2,
// lo+hi combined at the end. Weight cols 0..15 live in registers (80 regs);
// cols 16..19 come from a quad-interleaved smem tile (one broadcast LDS.128
// per row; the 4 quad-rows share a 64B region -> ~1 wavefront).
// 2048 warps total; launch_bounds(64,7) -> 1036 block slots >= 1024 blocks
// -> single balanced wave at 14 warps/SM.
__global__ void __launch_bounds__(64, 7) rnn_kernel(
    const float* __restrict__ x,      // [B, TLEN]
    const float* __restrict__ W_ih,   // [H]
    const float* __restrict__ W_hh,   // [H, H]
    const float* __restrict__ b_ih,   // [H]
    const float* __restrict__ b_hh,   // [H]
    const float* __restrict__ W_fc,   // [H]
    const float* __restrict__ b_fc,   // [1]
    float* __restrict__ out)          // [B]
{
    __shared__ float sW[H][H];                         // scaled W_hh
    __shared__ __align__(128) float sTail[5][4][4];    // [i][q][c] = W[5q+i][16+c]
    __shared__ float sWih[H], sPre[H], sWfc[H];
    __shared__ float sBfc;

    const int tid = threadIdx.x;
    const float SC = 2.8853900817779268f;              // 2*log2(e)

    for (int i = tid; i < H * H; i += 64) sW[i / H][i % H] = W_hh[i] * SC;
    if (tid < H) {
        sWih[tid] = W_ih[tid] * SC;
        sPre[tid] = (b_ih[tid] + b_hh[tid]) * SC;
        sWfc[tid] = W_fc[tid];
    }
    if (tid == 0) sBfc = b_fc[0];
    __syncthreads();
    // build quad-interleaved tail tile (cols 16..19 of each row).
    // 80 entries, 64 threads: STRIDED loop (R3 bug: plain `if (tid<80)` left
    // sTail[4][*][*] uninitialized with blockDim=64).
    for (int idx = tid; idx < 5 * 4 * 4; idx += 64) {
        int c = idx & 3, qq = (idx >> 2) & 3, ii = idx >> 4;
        sTail[ii][qq][c] = sW[5 * qq + ii][16 + c];
    }
    __syncthreads();

    const int q     = tid & 3;
    const int lane  = tid & 31;
    const int pbase = lane & ~3;
    const int batch = blockIdx.x * 16 + (tid >> 2);

    // register weights: rows 5q..5q+4, cols 0..15 as 8 packed pairs per row
    ull wk[5][8];
    float wih[5], pre[5];
    #pragma unroll
    for (int i = 0; i < 5; i++) {
        const int r = 5 * q + i;
        #pragma unroll
        for (int j = 0; j < 8; j++)
            wk[i][j] = pk(sW[r][2 * j], sW[r][2 * j + 1]);
        wih[i] = sWih[r];
        pre[i] = sPre[r];
    }

    float h[H];
    #pragma unroll
    for (int j = 0; j < H; j++) h[j] = 0.0f;

    const float* xp = x + (size_t)batch * TLEN;
    float4 xv = *(const float4*)xp;

    for (int t = 0; t < TLEN; t += 4) {
        float4 xn;
        if (t + 4 < TLEN) xn = *(const float4*)(xp + t + 4);
        const float xs[4] = {xv.x, xv.y, xv.z, xv.w};

        #pragma unroll
        for (int s = 0; s < 4; s++) {
            // pack h into 10 pairs (shared by all 5 rows)
            ull hp[10];
            #pragma unroll
            for (int j = 0; j < 10; j++) hp[j] = pk(h[2 * j], h[2 * j + 1]);

            float m[5];
            #pragma unroll
            for (int i = 0; i < 5; i++) {
                float a0 = fmaf(xs[s], wih[i], pre[i]);
                ull acc = fma2(wk[i][0], hp[0], pk(a0, 0.0f));
                #pragma unroll
                for (int j = 1; j < 8; j++)
                    acc = fma2(wk[i][j], hp[j], acc);
                // tail cols 16..19: one 16B broadcast LDS per row
                const ull* tp = (const ull*)sTail[i][q];
                acc = fma2(tp[0], hp[8], acc);
                acc = fma2(tp[1], hp[9], acc);
                float2 f = upk(acc);
                m[i] = tanh_ps(f.x + f.y);
            }
            // rebuild full h[20] across the quad (20 SHFL)
            #pragma unroll
            for (int q2 = 0; q2 < 4; q2++) {
                #pragma unroll
                for (int v = 0; v < 5; v++)
                    h[5 * q2 + v] = __shfl_sync(0xffffffffu, m[v], pbase + q2, 32);
            }
        }
        xv = xn;
    }

    if (q == 0) {
        float acc = sBfc;
        #pragma unroll
        for (int j = 0; j < H; j++) acc = fmaf(h[j], sWfc[j], acc);
        out[batch] = sigmoid1(acc);
    }
}

extern "C" void kernel_launch(void* const* d_in, const int* in_sizes, int n_in,
                              void* d_out, int out_size) {
    const float* x    = (const float*)d_in[0];
    const float* W_ih = (const float*)d_in[1];
    const float* W_hh = (const float*)d_in[2];
    const float* b_ih = (const float*)d_in[3];
    const float* b_hh = (const float*)d_in[4];
    const float* W_fc = (const float*)d_in[5];
    const float* b_fc = (const float*)d_in[6];
    float* out = (float*)d_out;

    const int B = in_sizes[0] / TLEN;   // 16384
    const int blocks = B / 16;          // 1024 blocks x 64 threads (4 thr/batch)
    rnn_kernel<<<blocks, 64>>>(x, W_ih, W_hh, b_ih, b_hh, W_fc, b_fc, out);
}

// round 5
// speedup vs baseline: 1.3974x; 1.3974x over previous
#include <cuda_runtime.h>
#include <cuda_bf16.h>

#define TLEN 2048
#define H 20
typedef unsigned long long ull;

// ---- packed f32x2 helpers ----
__device__ __forceinline__ ull pk(float lo, float hi) {
    ull r; asm("mov.b64 %0, {%1, %2};" : "=l"(r) : "f"(lo), "f"(hi)); return r;
}
__device__ __forceinline__ float2 upk(ull v) {
    float2 f; asm("mov.b64 {%0, %1}, %2;" : "=f"(f.x), "=f"(f.y) : "l"(v)); return f;
}
__device__ __forceinline__ ull fma2(ull a, ull b, ull c) {
    ull d; asm("fma.rn.f32x2 %0, %1, %2, %3;" : "=l"(d) : "l"(a), "l"(b), "l"(c)); return d;
}

// z pre-scaled by 2*log2(e): tanh(a) = 1 - 2/(exp2(z) + 1). |z|<~20: safe.
__device__ __forceinline__ float tanh_ps(float z) {
    float e; asm("ex2.approx.f32 %0, %1;" : "=f"(e) : "f"(z));
    float r; asm("rcp.approx.f32 %0, %1;" : "=f"(r) : "f"(e + 1.0f));
    return fmaf(-2.0f, r, 1.0f);
}
__device__ __forceinline__ float sigmoid1(float z) {
    float e; asm("ex2.approx.f32 %0, %1;" : "=f"(e) : "f"(z * -1.4426950408889634f));
    float r; asm("rcp.approx.f32 %0, %1;" : "=f"(r) : "f"(e + 1.0f));
    return r;
}

// 4 threads per batch (quad). Thread q owns hidden rows [5q, 5q+5).
// ALL weights register-resident: 5 rows x 10 packed (w_k,w_{k+1}) pairs =
// 100 regs. Inner loop has ZERO memory ops except one LDG.128 of x per 4
// steps. h lives only as 10 packed pairs; the 20 SHFLs per substep write
// pair halves directly.
// 32-thread blocks (8 batches), NO register cap (needs ~180 regs — the R4
// regression was launch_bounds forcing 128 regs -> local-memory spills).
// 2048 blocks -> 14 warps/SM, single balanced wave.
__global__ void __launch_bounds__(32) rnn_kernel(
    const float* __restrict__ x,      // [B, TLEN]
    const float* __restrict__ W_ih,   // [H]
    const float* __restrict__ W_hh,   // [H, H]
    const float* __restrict__ b_ih,   // [H]
    const float* __restrict__ b_hh,   // [H]
    const float* __restrict__ W_fc,   // [H]
    const float* __restrict__ b_fc,   // [1]
    float* __restrict__ out)          // [B]
{
    __shared__ float sW[H][H];
    __shared__ float sWih[H], sPre[H], sWfc[H];
    __shared__ float sBfc;

    const int tid = threadIdx.x;
    const float SC = 2.8853900817779268f;              // 2*log2(e)

    for (int i = tid; i < H * H; i += 32) sW[i / H][i % H] = W_hh[i] * SC;
    if (tid < H) {
        sWih[tid] = W_ih[tid] * SC;
        sPre[tid] = (b_ih[tid] + b_hh[tid]) * SC;
        sWfc[tid] = W_fc[tid];
    }
    if (tid == 0) sBfc = b_fc[0];
    __syncthreads();

    const int q     = tid & 3;
    const int pbase = tid & ~3;
    const int batch = blockIdx.x * 8 + (tid >> 2);

    // register weights: rows 5q..5q+4, all 20 cols as 10 packed pairs each
    ull wk[5][10];
    float wih[5], pre[5];
    #pragma unroll
    for (int i = 0; i < 5; i++) {
        const int r = 5 * q + i;
        #pragma unroll
        for (int j = 0; j < 10; j++)
            wk[i][j] = pk(sW[r][2 * j], sW[r][2 * j + 1]);
        wih[i] = sWih[r];
        pre[i] = sPre[r];
    }

    ull hp[10];
    #pragma unroll
    for (int j = 0; j < 10; j++) hp[j] = 0ull;

    const float* xp = x + (size_t)batch * TLEN;
    float4 xv = *(const float4*)xp;

    for (int t = 0; t < TLEN; t += 4) {
        float4 xn;
        if (t + 4 < TLEN) xn = *(const float4*)(xp + t + 4);
        const float xs[4] = {xv.x, xv.y, xv.z, xv.w};

        #pragma unroll
        for (int s = 0; s < 4; s++) {
            float m[5];
            #pragma unroll
            for (int i = 0; i < 5; i++) {
                float a0 = fmaf(xs[s], wih[i], pre[i]);
                ull acc = fma2(wk[i][0], hp[0], pk(a0, 0.0f));
                #pragma unroll
                for (int j = 1; j < 10; j++)
                    acc = fma2(wk[i][j], hp[j], acc);
                float2 f = upk(acc);
                m[i] = tanh_ps(f.x + f.y);
            }
            // rebuild packed h across the quad: h[r] lives in thread
            // pbase + r/5, register m[r%5]; 20 SHFLs, packed in pairs.
            #pragma unroll
            for (int j = 0; j < 10; j++) {
                const int r0 = 2 * j, r1 = 2 * j + 1;
                float lo = __shfl_sync(0xffffffffu, m[r0 % 5], pbase + r0 / 5, 32);
                float hi = __shfl_sync(0xffffffffu, m[r1 % 5], pbase + r1 / 5, 32);
                hp[j] = pk(lo, hi);
            }
        }
        xv = xn;
    }

    if (q == 0) {
        ull acc = pk(sBfc, 0.0f);
        #pragma unroll
        for (int j = 0; j < 10; j++)
            acc = fma2(hp[j], pk(sWfc[2 * j], sWfc[2 * j + 1]), acc);
        float2 f = upk(acc);
        out[batch] = sigmoid1(f.x + f.y);
    }
}

extern "C" void kernel_launch(void* const* d_in, const int* in_sizes, int n_in,
                              void* d_out, int out_size) {
    const float* x    = (const float*)d_in[0];
    const float* W_ih = (const float*)d_in[1];
    const float* W_hh = (const float*)d_in[2];
    const float* b_ih = (const float*)d_in[3];
    const float* b_hh = (const float*)d_in[4];
    const float* W_fc = (const float*)d_in[5];
    const float* b_fc = (const float*)d_in[6];
    float* out = (float*)d_out;

    const int B = in_sizes[0] / TLEN;   // 16384
    const int blocks = B / 8;           // 2048 blocks x 32 threads (4 thr/batch)
    rnn_kernel<<<blocks, 32>>>(x, W_ih, W_hh, b_ih, b_hh, W_fc, b_fc, out);
}